// round 3
// baseline (speedup 1.0000x reference)
#include <cuda_runtime.h>
#include <cuda_bf16.h>
#include <math_constants.h>

// BBOX_XFORM_CLIP = log(1000/16)
#define BBOX_XFORM_CLIP 4.135166556742356f

#define ROWS_PER_TILE 8              // 8 rows * 81 classes per tile
#define THREADS 256                  // 8 warps, 1 row per warp per tile
#define CTAS_PER_SM 8
#define NUM_SMS 148

#define BOX_TILE_BYTES   (ROWS_PER_TILE * 81 * 16)   // 10368
#define SCORE_TILE_BYTES (ROWS_PER_TILE * 81 * 4)    //  2592

// img dims may arrive as int32 or float32; disambiguate by plausibility.
__device__ __forceinline__ float load_dim(const void* p) {
    int iv = *(const int*)p;
    if (iv > 0 && iv < (1 << 20)) return (float)iv;
    return __int_as_float(iv);
}

__global__ void __launch_bounds__(THREADS)
postproc_kernel(const float* __restrict__ logits,       // [N,81]
                const float* __restrict__ regr,         // [N,4]
                const float* __restrict__ prop,         // [N,4]
                const void*  __restrict__ imw_p,
                const void*  __restrict__ imh_p,
                float* __restrict__ boxes_out,          // [N*81,4]
                float* __restrict__ scores_out,         // [N*81]
                int N)
{
    // double-buffered staging: [2][boxes | scores]
    __shared__ alignas(16) float s_boxes [2][ROWS_PER_TILE * 81 * 4]; // 2x10368B
    __shared__ alignas(16) float s_scores[2][ROWS_PER_TILE * 81];     // 2x 2592B

    const int warp = threadIdx.x >> 5;
    const int lane = threadIdx.x & 31;

    const float wmax = load_dim(imw_p) - 1.0f;
    const float hmax = load_dim(imh_p) - 1.0f;

    const int num_tiles = (N + ROWS_PER_TILE - 1) / ROWS_PER_TILE;

    int p = 0;
    for (int t = blockIdx.x; t < num_tiles; t += gridDim.x, p ^= 1) {
        const int n = t * ROWS_PER_TILE + warp;     // this warp's row
        const bool full_tile = (t * ROWS_PER_TILE + ROWS_PER_TILE) <= N;

        float4 box;
        float sc0 = 0.f, sc1 = 0.f, sc2 = 0.f;

        if (n < N) {
            // ---------------- softmax over 81 logits ----------------
            const float* lrow = logits + (size_t)n * 81;
            float v0 = lrow[lane];
            float v1 = lrow[lane + 32];
            float v2 = (lane < 17) ? lrow[lane + 64] : -CUDART_INF_F;

            float m = fmaxf(fmaxf(v0, v1), v2);
            #pragma unroll
            for (int o = 16; o; o >>= 1)
                m = fmaxf(m, __shfl_xor_sync(0xffffffffu, m, o));

            float e0 = __expf(v0 - m);
            float e1 = __expf(v1 - m);
            float e2 = (lane < 17) ? __expf(v2 - m) : 0.0f;

            float s = e0 + e1 + e2;
            #pragma unroll
            for (int o = 16; o; o >>= 1)
                s += __shfl_xor_sync(0xffffffffu, s, o);
            const float inv = 1.0f / s;
            sc0 = e0 * inv; sc1 = e1 * inv; sc2 = e2 * inv;

            // ---------------- bbox decode (all lanes redundantly) ------------
            const float4 b  = reinterpret_cast<const float4*>(prop)[n];
            const float4 rc = reinterpret_cast<const float4*>(regr)[n];

            const float w  = b.z - b.x + 1.0f;
            const float h  = b.w - b.y + 1.0f;
            const float cx = b.x + 0.5f * w;
            const float cy = b.y + 0.5f * h;

            const float dx = rc.x * 0.1f;
            const float dy = rc.y * 0.1f;
            const float dw = fminf(rc.z * 0.2f, BBOX_XFORM_CLIP);
            const float dh = fminf(rc.w * 0.2f, BBOX_XFORM_CLIP);

            const float pcx = dx * w + cx;
            const float pcy = dy * h + cy;
            const float pw  = __expf(dw) * w;
            const float ph  = __expf(dh) * h;

            float x1 = pcx - 0.5f * pw;
            float y1 = pcy - 0.5f * ph;
            float x2 = pcx + 0.5f * pw - 1.0f;
            float y2 = pcy + 0.5f * ph - 1.0f;

            // max(...,0) then clip(0,max) == clamp to [0,max]
            x1 = fminf(fmaxf(x1, 0.0f), wmax);
            y1 = fminf(fmaxf(y1, 0.0f), hmax);
            x2 = fminf(fmaxf(x2, 0.0f), wmax);
            y2 = fminf(fmaxf(y2, 0.0f), hmax);
            box = make_float4(x1, y1, x2, y2);
        }

        if (full_tile) {
            // ---- stage to SMEM buffer p ----
            if (n < N) {
                float4* sb = reinterpret_cast<float4*>(s_boxes[p]) + warp * 81;
                sb[lane]      = box;
                sb[lane + 32] = box;
                if (lane < 17) sb[lane + 64] = box;

                float* ss = s_scores[p] + warp * 81;
                ss[lane]      = sc0;
                ss[lane + 32] = sc1;
                if (lane < 17) ss[lane + 64] = sc2;
            }
            __syncthreads();

            if (threadIdx.x == 0) {
                asm volatile("fence.proxy.async.shared::cta;" ::: "memory");
                unsigned sb_addr = (unsigned)__cvta_generic_to_shared(s_boxes[p]);
                unsigned ss_addr = (unsigned)__cvta_generic_to_shared(s_scores[p]);
                char* gboxes  = (char*)boxes_out  + (size_t)t * BOX_TILE_BYTES;
                char* gscores = (char*)scores_out + (size_t)t * SCORE_TILE_BYTES;
                asm volatile(
                    "cp.async.bulk.global.shared::cta.bulk_group [%0], [%1], %2;"
                    :: "l"(gboxes), "r"(sb_addr), "n"(BOX_TILE_BYTES) : "memory");
                asm volatile(
                    "cp.async.bulk.global.shared::cta.bulk_group [%0], [%1], %2;"
                    :: "l"(gscores), "r"(ss_addr), "n"(SCORE_TILE_BYTES) : "memory");
                asm volatile("cp.async.bulk.commit_group;" ::: "memory");
                // keep at most 1 group in flight -> buffer p^1 is free after this
                asm volatile("cp.async.bulk.wait_group.read 1;" ::: "memory");
            }
            __syncthreads();
        } else if (n < N) {
            // rare partial tail tile: direct stores
            float4* bo = reinterpret_cast<float4*>(boxes_out) + (size_t)n * 81;
            bo[lane]      = box;
            bo[lane + 32] = box;
            if (lane < 17) bo[lane + 64] = box;
            float* so = scores_out + (size_t)n * 81;
            so[lane]      = sc0;
            so[lane + 32] = sc1;
            if (lane < 17) so[lane + 64] = sc2;
        }
    }

    // drain all outstanding bulk groups before the CTA retires
    if (threadIdx.x == 0)
        asm volatile("cp.async.bulk.wait_group.read 0;" ::: "memory");
}

extern "C" void kernel_launch(void* const* d_in, const int* in_sizes, int n_in,
                              void* d_out, int out_size) {
    const float* logits = (const float*)d_in[0];
    const float* regr   = (const float*)d_in[1];
    const float* prop   = (const float*)d_in[2];
    const void*  imw    = d_in[3];
    const void*  imh    = d_in[4];

    const int N = in_sizes[0] / 81;          // 262144

    float* boxes  = (float*)d_out;           // N*81*4 floats
    float* scores = boxes + (size_t)N * 81 * 4;

    const int blocks = CTAS_PER_SM * NUM_SMS;    // 1184 persistent CTAs
    postproc_kernel<<<blocks, THREADS>>>(logits, regr, prop, imw, imh,
                                         boxes, scores, N);
}